// round 2
// baseline (speedup 1.0000x reference)
#include <cuda_runtime.h>
#include <cstddef>

#define BATCH 8
#define LFRM  64
#define CH    3
#define HH    224
#define WW    224
#define HWSZ  (HH*WW)            // 50176
#define FRAMES (BATCH*LFRM)      // 512
#define PAIRS  (BATCH*(LFRM-1))  // 504
#define MSEL   16
#define EPSF   1e-6f

// ---------------- scratch (static device globals; no allocation) -------------
__device__ float  g_y[(size_t)FRAMES * HWSZ];   // conv outputs, ~98 MB
__device__ double g_ds[PAIRS];                  // per-pair diff scores
__device__ int    g_idx[BATCH * MSEL];          // selected frame indices

// ---------------- kernel 1: 7x7 conv, 3->1 ch, pad 3 ------------------------
// block (32,8): tile 128 wide x 8 tall outputs, each thread 4 horizontal pixels
__global__ __launch_bounds__(256) void conv_kernel(const float* __restrict__ x,
                                                   const float* __restrict__ wgt)
{
    __shared__ __align__(16) float tile[3 * 14 * 136];
    __shared__ float wsh[152];

    const int tid = threadIdx.y * 32 + threadIdx.x;
    if (tid < 147) wsh[tid] = wgt[tid];

    const int f   = blockIdx.z;
    const int gy0 = blockIdx.y * 8  - 3;
    const int gx0 = blockIdx.x * 128 - 3;
    const float* xf = x + (size_t)f * (CH * HWSZ);

    // cooperative halo load with zero padding
    for (int i = tid; i < 3 * 14 * 136; i += 256) {
        int c   = i / (14 * 136);
        int rem = i - c * (14 * 136);
        int r   = rem / 136;
        int col = rem - r * 136;
        int gr = gy0 + r, gc = gx0 + col;
        float v = 0.f;
        if ((unsigned)gr < HH && (unsigned)gc < WW)
            v = __ldg(xf + (size_t)c * HWSZ + gr * WW + gc);
        tile[i] = v;
    }
    __syncthreads();

    const int tx = threadIdx.x, ty = threadIdx.y;
    const int ocol = blockIdx.x * 128 + tx * 4;
    if (ocol >= WW) return;

    float a0 = 0.f, a1 = 0.f, a2 = 0.f, a3 = 0.f;
#pragma unroll
    for (int c = 0; c < 3; c++) {
#pragma unroll
        for (int u = 0; u < 7; u++) {
            const float* rp = &tile[c * (14 * 136) + (ty + u) * 136 + tx * 4];
            float4 p0 = *(const float4*)(rp);
            float4 p1 = *(const float4*)(rp + 4);
            float4 p2 = *(const float4*)(rp + 8);
            float r[12] = {p0.x, p0.y, p0.z, p0.w,
                           p1.x, p1.y, p1.z, p1.w,
                           p2.x, p2.y, p2.z, p2.w};
            const float* wp = &wsh[c * 49 + u * 7];
#pragma unroll
            for (int v = 0; v < 7; v++) {
                float wv = wp[v];
                a0 = fmaf(wv, r[v],     a0);
                a1 = fmaf(wv, r[v + 1], a1);
                a2 = fmaf(wv, r[v + 2], a2);
                a3 = fmaf(wv, r[v + 3], a3);
            }
        }
    }
    const int orow = blockIdx.y * 8 + ty;
    float4 out = make_float4(a0, a1, a2, a3);
    *(float4*)&g_y[(size_t)f * HWSZ + (size_t)orow * WW + ocol] = out;
}

// ---------------- kernel 2: per-pair sum |y_l - y_{l+1} + eps| ---------------
__global__ __launch_bounds__(256) void diff_kernel()
{
    const int p = blockIdx.x;          // 0..503
    const int b = p / (LFRM - 1);
    const int l = p - b * (LFRM - 1);
    const float4* A = (const float4*)&g_y[(size_t)(b * LFRM + l)     * HWSZ];
    const float4* Bp = (const float4*)&g_y[(size_t)(b * LFRM + l + 1) * HWSZ];

    double s = 0.0;
    for (int i = threadIdx.x; i < HWSZ / 4; i += 256) {
        float4 a = A[i], q = Bp[i];
        s += (double)fabsf(a.x - q.x + EPSF)
           + (double)fabsf(a.y - q.y + EPSF)
           + (double)fabsf(a.z - q.z + EPSF)
           + (double)fabsf(a.w - q.w + EPSF);
    }

    __shared__ double sd[256];
    sd[threadIdx.x] = s;
    __syncthreads();
    for (int off = 128; off > 0; off >>= 1) {
        if (threadIdx.x < off) sd[threadIdx.x] += sd[threadIdx.x + off];
        __syncthreads();
    }
    if (threadIdx.x == 0) g_ds[p] = sd[0];
}

// ---------------- kernel 3: sqrt / normalize / cumsum / argmin ---------------
// ratio = 16/64 = 0.25 ; exponent = sqrt(0.25) = 0.5 -> dsp = sqrt(diff_score)
__global__ void select_kernel()
{
    const int b = threadIdx.x;
    if (b >= BATCH) return;

    double dsp[LFRM - 1];
    double s = 0.0;
    for (int l = 0; l < LFRM - 1; l++) {
        double d = sqrt(g_ds[b * (LFRM - 1) + l]);
        dsp[l] = d;
        s += d;
    }
    double cums[LFRM - 1];
    double c = 0.0;
    for (int l = 0; l < LFRM - 1; l++) {
        c += dsp[l] / s;
        cums[l] = c;
    }
    const float interval = 1.0f / (float)(MSEL - 1);
    for (int m = 0; m < MSEL; m++) {
        double target = (double)((float)m * interval);
        double best = 1e300;
        int bi = 0;
        for (int l = 0; l < LFRM - 1; l++) {
            double d = fabs(cums[l] - target);
            if (d < best) { best = d; bi = l; }   // strict '<' => first occurrence
        }
        g_idx[b * MSEL + m] = bi;
    }
}

// ---------------- kernel 4: gather selected frames ---------------------------
__global__ __launch_bounds__(256) void gather_kernel(const float* __restrict__ x,
                                                     float* __restrict__ out)
{
    const int bm = blockIdx.y;             // 0..127
    const int b  = bm >> 4;
    const int src = b * LFRM + g_idx[bm];
    const float4* sp = (const float4*)(x + (size_t)src * (CH * HWSZ));
    float4* dp = (float4*)(out + (size_t)bm * (CH * HWSZ));
    const int i = blockIdx.x * 256 + threadIdx.x;   // 147*256 = 37632 exact
    dp[i] = sp[i];
}

// ---------------- launcher ---------------------------------------------------
extern "C" void kernel_launch(void* const* d_in, const int* in_sizes, int n_in,
                              void* d_out, int out_size)
{
    const float* x = nullptr;
    const float* w = nullptr;
    for (int i = 0; i < n_in; i++) {
        if (in_sizes[i] == FRAMES * CH * HWSZ) x = (const float*)d_in[i];
        else if (in_sizes[i] == CH * 49)       w = (const float*)d_in[i];
    }

    conv_kernel<<<dim3(2, 28, FRAMES), dim3(32, 8)>>>(x, w);
    diff_kernel<<<PAIRS, 256>>>();
    select_kernel<<<1, 32>>>();
    gather_kernel<<<dim3(147, BATCH * MSEL), 256>>>(x, (float*)d_out);
}

// round 3
// speedup vs baseline: 1.1045x; 1.1045x over previous
#include <cuda_runtime.h>
#include <cstddef>

#define BATCH 8
#define LFRM  64
#define CH    3
#define HH    224
#define WW    224
#define HWSZ  (HH*WW)            // 50176
#define FRAMES (BATCH*LFRM)      // 512
#define PAIRS  (BATCH*(LFRM-1))  // 504
#define MSEL   16
#define EPSF   1e-6f

// tile geometry for conv: full-width rows, 32 output rows per block
#define TROWS   38               // 32 + 6 halo
#define TSTRIDE 232              // 230 used (224 + 6 halo), padded
#define SMEM_FLOATS (296 + CH*TROWS*TSTRIDE)   // 296 = 147 ull weight pairs (1176B) rounded to 16B
#define SMEM_BYTES  (SMEM_FLOATS * 4)

// ---------------- scratch (static device globals; no allocation) -------------
__device__ float  g_y[(size_t)FRAMES * HWSZ];   // conv outputs, ~98 MB
__device__ double g_ds[PAIRS];                  // per-pair diff scores
__device__ int    g_idx[BATCH * MSEL];          // selected frame indices

// packed f32x2 helpers (sm_103a)
#define PACK2(p, lo, hi) asm("mov.b64 %0, {%1, %2};" : "=l"(p) : "f"(lo), "f"(hi))
#define FMA2(acc, a, b)  asm("fma.rn.f32x2 %0, %1, %2, %0;" : "+l"(acc) : "l"(a), "l"(b))

// ---------------- kernel 1: 7x7 conv, 3->1 ch, pad 3, f32x2 packed ----------
// 224 threads: tx = tid%28 (8 output cols each), ty = tid/28 (4 output rows each)
// block output: 224 wide x 32 tall; grid (7, 512)
__global__ __launch_bounds__(224, 2) void conv2_kernel(const float* __restrict__ x,
                                                       const float* __restrict__ wgt)
{
    extern __shared__ float sm[];
    unsigned long long* w2 = (unsigned long long*)sm;   // 147 packed weight pairs
    float* tile = sm + 296;                             // [3][38][232]

    const int tid = threadIdx.x;        // 0..223
    const int f   = blockIdx.y;
    const int by  = blockIdx.x;         // 0..6
    const int gy0 = by * 32 - 3;
    const float* xf = x + (size_t)f * (CH * HWSZ);

    // pack weights (w, w)
    if (tid < 147) {
        float w = wgt[tid];
        unsigned long long pw; PACK2(pw, w, w);
        w2[tid] = pw;
    }
    // zero the 6 halo columns of every row
    if (tid < 6) {
        const int pc = (tid < 3) ? tid : tid + 224;   // cols 0,1,2,227,228,229
        for (int ct = 0; ct < CH * TROWS; ct++) tile[ct * TSTRIDE + pc] = 0.f;
    }
    // interior: one coalesced float per thread per (channel,row)
    for (int ct = 0; ct < CH * TROWS; ct++) {
        const int c = ct / TROWS, t = ct - c * TROWS;
        const int gr = gy0 + t;
        float v = 0.f;
        if ((unsigned)gr < (unsigned)HH) v = xf[(size_t)c * HWSZ + gr * WW + tid];
        tile[ct * TSTRIDE + 3 + tid] = v;
    }
    __syncthreads();

    const int tx = tid % 28, tyq = tid / 28;
    const int colbase = tx * 8;

    unsigned long long acc[4][4];
#pragma unroll
    for (int rr = 0; rr < 4; rr++)
#pragma unroll
        for (int p = 0; p < 4; p++) acc[rr][p] = 0ull;

#pragma unroll
    for (int t = 0; t < 10; t++) {
#pragma unroll
        for (int c = 0; c < 3; c++) {
            const float* rp = &tile[(c * TROWS + tyq * 4 + t) * TSTRIDE + colbase];
            float4 A = *(const float4*)(rp);
            float4 B = *(const float4*)(rp + 4);
            float4 C = *(const float4*)(rp + 8);
            float2 D = *(const float2*)(rp + 12);
            float fl[14] = {A.x, A.y, A.z, A.w, B.x, B.y, B.z, B.w,
                            C.x, C.y, C.z, C.w, D.x, D.y};
            unsigned long long pr[13];
#pragma unroll
            for (int j = 0; j < 13; j++) PACK2(pr[j], fl[j], fl[j + 1]);

#pragma unroll
            for (int rr = 0; rr < 4; rr++) {
                const int u = t - rr;                 // compile-time after unroll
                if (u < 0 || u > 6) continue;
                const unsigned long long* wrow = &w2[c * 49 + u * 7];
#pragma unroll
                for (int v = 0; v < 7; v++) {
                    const unsigned long long wv = wrow[v];
                    FMA2(acc[rr][0], wv, pr[v]);
                    FMA2(acc[rr][1], wv, pr[v + 2]);
                    FMA2(acc[rr][2], wv, pr[v + 4]);
                    FMA2(acc[rr][3], wv, pr[v + 6]);
                }
            }
        }
    }

    const int oybase = by * 32 + tyq * 4;
#pragma unroll
    for (int rr = 0; rr < 4; rr++) {
        float* op = &g_y[(size_t)f * HWSZ + (size_t)(oybase + rr) * WW + colbase];
        ulonglong2 s0, s1;
        s0.x = acc[rr][0]; s0.y = acc[rr][1];
        s1.x = acc[rr][2]; s1.y = acc[rr][3];
        *(ulonglong2*)(op)     = s0;
        *(ulonglong2*)(op + 4) = s1;
    }
}

// ---------------- kernel 2: per-pair sum |y_l - y_{l+1} + eps| ---------------
__global__ __launch_bounds__(256) void diff_kernel()
{
    const int p = blockIdx.x;          // 0..503
    const int b = p / (LFRM - 1);
    const int l = p - b * (LFRM - 1);
    const float4* A  = (const float4*)&g_y[(size_t)(b * LFRM + l)     * HWSZ];
    const float4* Bp = (const float4*)&g_y[(size_t)(b * LFRM + l + 1) * HWSZ];

    double s = 0.0;
    for (int i = threadIdx.x; i < HWSZ / 4; i += 256) {
        float4 a = A[i], q = Bp[i];
        s += (double)fabsf(a.x - q.x + EPSF)
           + (double)fabsf(a.y - q.y + EPSF)
           + (double)fabsf(a.z - q.z + EPSF)
           + (double)fabsf(a.w - q.w + EPSF);
    }

    __shared__ double sd[256];
    sd[threadIdx.x] = s;
    __syncthreads();
    for (int off = 128; off > 0; off >>= 1) {
        if (threadIdx.x < off) sd[threadIdx.x] += sd[threadIdx.x + off];
        __syncthreads();
    }
    if (threadIdx.x == 0) g_ds[p] = sd[0];
}

// ---------------- kernel 3: sqrt / normalize / cumsum / argmin ---------------
// ratio = 16/64 = 0.25 ; exponent = sqrt(0.25) = 0.5 -> dsp = sqrt(diff_score)
__global__ void select_kernel()
{
    const int b = threadIdx.x;
    if (b >= BATCH) return;

    double dsp[LFRM - 1];
    double s = 0.0;
    for (int l = 0; l < LFRM - 1; l++) {
        double d = sqrt(g_ds[b * (LFRM - 1) + l]);
        dsp[l] = d;
        s += d;
    }
    double cums[LFRM - 1];
    double c = 0.0;
    for (int l = 0; l < LFRM - 1; l++) {
        c += dsp[l] / s;
        cums[l] = c;
    }
    const float interval = 1.0f / (float)(MSEL - 1);
    for (int m = 0; m < MSEL; m++) {
        double target = (double)((float)m * interval);
        double best = 1e300;
        int bi = 0;
        for (int l = 0; l < LFRM - 1; l++) {
            double d = fabs(cums[l] - target);
            if (d < best) { best = d; bi = l; }   // strict '<' => first occurrence
        }
        g_idx[b * MSEL + m] = bi;
    }
}

// ---------------- kernel 4: gather selected frames ---------------------------
__global__ __launch_bounds__(256) void gather_kernel(const float* __restrict__ x,
                                                     float* __restrict__ out)
{
    const int bm = blockIdx.y;             // 0..127
    const int b  = bm >> 4;
    const int src = b * LFRM + g_idx[bm];
    const float4* sp = (const float4*)(x + (size_t)src * (CH * HWSZ));
    float4* dp = (float4*)(out + (size_t)bm * (CH * HWSZ));
    const int i = blockIdx.x * 256 + threadIdx.x;   // 147*256 = 37632 exact
    dp[i] = sp[i];
}

// ---------------- launcher ---------------------------------------------------
extern "C" void kernel_launch(void* const* d_in, const int* in_sizes, int n_in,
                              void* d_out, int out_size)
{
    const float* x = nullptr;
    const float* w = nullptr;
    for (int i = 0; i < n_in; i++) {
        if (in_sizes[i] == FRAMES * CH * HWSZ) x = (const float*)d_in[i];
        else if (in_sizes[i] == CH * 49)       w = (const float*)d_in[i];
    }

    cudaFuncSetAttribute(conv2_kernel,
                         cudaFuncAttributeMaxDynamicSharedMemorySize, SMEM_BYTES);
    conv2_kernel<<<dim3(7, FRAMES), 224, SMEM_BYTES>>>(x, w);
    diff_kernel<<<PAIRS, 256>>>();
    select_kernel<<<1, 32>>>();
    gather_kernel<<<dim3(147, BATCH * MSEL), 256>>>(x, (float*)d_out);
}

// round 4
// speedup vs baseline: 1.8811x; 1.7031x over previous
#include <cuda_runtime.h>
#include <cstddef>

#define BATCH 8
#define LFRM  64
#define CH    3
#define HH    224
#define WW    224
#define HWSZ  (HH*WW)            // 50176
#define FRAMES (BATCH*LFRM)      // 512
#define PAIRS  (BATCH*(LFRM-1))  // 504
#define MSEL   16
#define EPSF   1e-6f

// ---------------- scratch (static device globals; no allocation) -------------
__device__ double g_ds2[PAIRS * 2];             // per-(pair,half) partial diff scores
__device__ int    g_idx[BATCH * MSEL];          // selected frame indices

// ============================================================================
// kernel 1: fused channel-sum + 7x7 box + pairwise |w0*box + eps| reduction
//
// y_l - y_{l+1} = w0 * box7x7( sum_c (x_l - x_{l+1}) )   (uniform w, bias cancels)
//
// grid (2, PAIRS): x = half (rows 0..111 / 112..223), y = pair index.
// 224 threads; thread t owns output column t.
// Horizontal 7-tap via smem row buffers; vertical 7-tap via register ring
// (fresh 7-term sum per output row -> no accumulation drift).
// ============================================================================
__global__ __launch_bounds__(224) void pairdiff_kernel(const float* __restrict__ x,
                                                       const float* __restrict__ wgt)
{
    __shared__ __align__(16) float buf[2][4][232];   // double-banked 4-row groups
    __shared__ double sd[224];

    const int t    = threadIdx.x;                    // 0..223
    const int half = blockIdx.x;                     // 0..1
    const int p    = blockIdx.y;                     // 0..503
    const int b    = p / (LFRM - 1);
    const int l    = p - b * (LFRM - 1);
    const int r0   = half * 112;

    const float w0 = __ldg(wgt);                     // uniform conv weight
    const float* xl = x + (size_t)(b * LFRM + l) * (CH * HWSZ);
    const float* xr = xl + (size_t)(CH * HWSZ);      // next frame

    // zero halo columns (positions 0..2, 227..229) of all 8 row buffers
    if (t < 6) {
        const int pc = (t < 3) ? t : 224 + t;        // 0,1,2,227,228,229
        for (int bk = 0; bk < 2; bk++)
            for (int e = 0; e < 4; e++) buf[bk][e][pc] = 0.f;
    }
    __syncthreads();

    float  hb[8];                                    // hbox register ring
#pragma unroll
    for (int k = 0; k < 8; k++) hb[k] = 0.f;
    double acc0 = 0.0, acc1 = 0.0;

    // input rows i = r0 - 3 + j, j = 0..119 (15 packs of 8 = 2 banked groups of 4)
#pragma unroll 1
    for (int pk = 0; pk < 15; pk++) {
#pragma unroll
        for (int bk = 0; bk < 2; bk++) {
            // ---- load 4 channel-summed difference rows into this bank ----
#pragma unroll
            for (int e = 0; e < 4; e++) {
                const int j = pk * 8 + bk * 4 + e;
                const int i = r0 - 3 + j;
                float d = 0.f;
                if ((unsigned)i < (unsigned)HH) {
                    const size_t off = (size_t)i * WW + t;
                    float a0 = __ldg(xl + off);
                    float a1 = __ldg(xl + HWSZ + off);
                    float a2 = __ldg(xl + 2 * HWSZ + off);
                    float b0 = __ldg(xr + off);
                    float b1 = __ldg(xr + HWSZ + off);
                    float b2 = __ldg(xr + 2 * HWSZ + off);
                    d = (a0 + a1 + a2) - (b0 + b1 + b2);
                }
                buf[bk][e][3 + t] = d;
            }
            __syncthreads();

            // ---- horizontal 7-tap box into ring, then emit output rows ----
#pragma unroll
            for (int e = 0; e < 4; e++) {
                const int j  = pk * 8 + bk * 4 + e;
                const int re = bk * 4 + e;           // ring slot (static)
                const float* rp = &buf[bk][e][t];    // covers cols t-3..t+3
                hb[re] = ((rp[0] + rp[1]) + (rp[2] + rp[3]))
                       + ((rp[4] + rp[5]) + rp[6]);

                if (j >= 6 && j <= 117) {            // output row r = r0 + j - 6
                    float vs = ((hb[(re)     & 7] + hb[(re + 7) & 7])
                             +  (hb[(re + 6) & 7] + hb[(re + 5) & 7]))
                             + ((hb[(re + 4) & 7] + hb[(re + 3) & 7])
                             +   hb[(re + 2) & 7]);
                    float pix = fabsf(fmaf(w0, vs, EPSF));
                    if (j & 1) acc1 += (double)pix;
                    else       acc0 += (double)pix;
                }
            }
            __syncthreads();   // all reads of this bank done before next reuse
        }
    }

    // ---- block reduction of double partials ----
    sd[t] = acc0 + acc1;
    __syncthreads();
    if (t < 112) sd[t] += sd[t + 112];
    __syncthreads();
    if (t < 56)  sd[t] += sd[t + 56];
    __syncthreads();
    if (t < 28)  sd[t] += sd[t + 28];
    __syncthreads();
    if (t < 14)  sd[t] += sd[t + 14];
    __syncthreads();
    if (t < 7)   sd[t] += sd[t + 7];
    __syncthreads();
    if (t == 0) {
        double s = sd[0];
        for (int k = 1; k < 7; k++) s += sd[k];
        g_ds2[p * 2 + half] = s;
    }
}

// ---------------- kernel 2: sqrt / normalize / cumsum / argmin ---------------
// ratio = 16/64 = 0.25 ; exponent = sqrt(0.25) = 0.5 -> dsp = sqrt(diff_score)
__global__ void select_kernel()
{
    const int b = threadIdx.x;
    if (b >= BATCH) return;

    double dsp[LFRM - 1];
    double s = 0.0;
    for (int l = 0; l < LFRM - 1; l++) {
        const int p = b * (LFRM - 1) + l;
        double d = sqrt(g_ds2[p * 2] + g_ds2[p * 2 + 1]);
        dsp[l] = d;
        s += d;
    }
    double cums[LFRM - 1];
    double c = 0.0;
    for (int l = 0; l < LFRM - 1; l++) {
        c += dsp[l] / s;
        cums[l] = c;
    }
    const float interval = 1.0f / (float)(MSEL - 1);
    for (int m = 0; m < MSEL; m++) {
        double target = (double)((float)m * interval);
        double best = 1e300;
        int bi = 0;
        for (int l = 0; l < LFRM - 1; l++) {
            double d = fabs(cums[l] - target);
            if (d < best) { best = d; bi = l; }   // strict '<' => first occurrence
        }
        g_idx[b * MSEL + m] = bi;
    }
}

// ---------------- kernel 3: gather selected frames ---------------------------
__global__ __launch_bounds__(256) void gather_kernel(const float* __restrict__ x,
                                                     float* __restrict__ out)
{
    const int bm = blockIdx.y;             // 0..127
    const int b  = bm >> 4;
    const int src = b * LFRM + g_idx[bm];
    const float4* sp = (const float4*)(x + (size_t)src * (CH * HWSZ));
    float4* dp = (float4*)(out + (size_t)bm * (CH * HWSZ));
    const int i = blockIdx.x * 256 + threadIdx.x;   // 147*256 = 37632 exact
    dp[i] = sp[i];
}

// ---------------- launcher ---------------------------------------------------
extern "C" void kernel_launch(void* const* d_in, const int* in_sizes, int n_in,
                              void* d_out, int out_size)
{
    const float* x = nullptr;
    const float* w = nullptr;
    for (int i = 0; i < n_in; i++) {
        if (in_sizes[i] == FRAMES * CH * HWSZ) x = (const float*)d_in[i];
        else if (in_sizes[i] == CH * 49)       w = (const float*)d_in[i];
    }

    pairdiff_kernel<<<dim3(2, PAIRS), 224>>>(x, w);
    select_kernel<<<1, 32>>>();
    gather_kernel<<<dim3(147, BATCH * MSEL), 256>>>(x, (float*)d_out);
}

// round 8
// speedup vs baseline: 1.8902x; 1.0048x over previous
#include <cuda_runtime.h>
#include <cstddef>

#define BATCH 8
#define LFRM  64
#define CH    3
#define HH    224
#define WW    224
#define HWSZ  (HH*WW)            // 50176
#define FRAMES (BATCH*LFRM)      // 512
#define PAIRS  (BATCH*(LFRM-1))  // 504
#define MSEL   16
#define EPSF   1e-6f

// ---------------- scratch (static device globals; no allocation) -------------
__device__ double g_ds2[PAIRS * 2];             // per-(pair,half) partial diff scores
__device__ int    g_idx[BATCH * MSEL];          // selected frame indices

// ============================================================================
// kernel 1: fused channel-sum + 7x7 box + pairwise |w0*box + eps| reduction
//
// y_l - y_{l+1} = w0 * box7x7( sum_c (x_l - x_{l+1}) )   (uniform w, bias cancels)
//
// grid (2, PAIRS): x = half (rows 0..111 / 112..223), y = pair index.
// 224 threads; thread t owns output column t.
// Horizontal 7-tap via smem row buffers; vertical 7-tap via register ring
// (fresh 7-term sum per output row -> no accumulation drift).
// ============================================================================
__global__ __launch_bounds__(224) void pairdiff_kernel(const float* __restrict__ x,
                                                       const float* __restrict__ wgt)
{
    __shared__ __align__(16) float buf[2][4][232];   // double-banked 4-row groups
    __shared__ double sd[224];

    const int t    = threadIdx.x;                    // 0..223
    const int half = blockIdx.x;                     // 0..1
    const int p    = blockIdx.y;                     // 0..503
    const int b    = p / (LFRM - 1);
    const int l    = p - b * (LFRM - 1);
    const int r0   = half * 112;

    const float w0 = __ldg(wgt);                     // uniform conv weight
    const float* xl = x + (size_t)(b * LFRM + l) * (CH * HWSZ);
    const float* xr = xl + (size_t)(CH * HWSZ);      // next frame

    // zero halo columns (positions 0..2, 227..229) of all 8 row buffers
    if (t < 6) {
        const int pc = (t < 3) ? t : 224 + t;        // 0,1,2,227,228,229
        for (int bk = 0; bk < 2; bk++)
            for (int e = 0; e < 4; e++) buf[bk][e][pc] = 0.f;
    }
    __syncthreads();

    float  hb[8];                                    // hbox register ring
#pragma unroll
    for (int k = 0; k < 8; k++) hb[k] = 0.f;
    double acc0 = 0.0, acc1 = 0.0;

    // input rows i = r0 - 3 + j, j = 0..119 (15 packs of 8 = 2 banked groups of 4)
#pragma unroll 1
    for (int pk = 0; pk < 15; pk++) {
#pragma unroll
        for (int bk = 0; bk < 2; bk++) {
            // ---- load 4 channel-summed difference rows into this bank ----
#pragma unroll
            for (int e = 0; e < 4; e++) {
                const int j = pk * 8 + bk * 4 + e;
                const int i = r0 - 3 + j;
                float d = 0.f;
                if ((unsigned)i < (unsigned)HH) {
                    const size_t off = (size_t)i * WW + t;
                    float a0 = __ldg(xl + off);
                    float a1 = __ldg(xl + HWSZ + off);
                    float a2 = __ldg(xl + 2 * HWSZ + off);
                    float b0 = __ldg(xr + off);
                    float b1 = __ldg(xr + HWSZ + off);
                    float b2 = __ldg(xr + 2 * HWSZ + off);
                    d = (a0 + a1 + a2) - (b0 + b1 + b2);
                }
                buf[bk][e][3 + t] = d;
            }
            __syncthreads();

            // ---- horizontal 7-tap box into ring, then emit output rows ----
#pragma unroll
            for (int e = 0; e < 4; e++) {
                const int j  = pk * 8 + bk * 4 + e;
                const int re = bk * 4 + e;           // ring slot (static)
                const float* rp = &buf[bk][e][t];    // covers cols t-3..t+3
                hb[re] = ((rp[0] + rp[1]) + (rp[2] + rp[3]))
                       + ((rp[4] + rp[5]) + rp[6]);

                if (j >= 6 && j <= 117) {            // output row r = r0 + j - 6
                    float vs = ((hb[(re)     & 7] + hb[(re + 7) & 7])
                             +  (hb[(re + 6) & 7] + hb[(re + 5) & 7]))
                             + ((hb[(re + 4) & 7] + hb[(re + 3) & 7])
                             +   hb[(re + 2) & 7]);
                    float pix = fabsf(fmaf(w0, vs, EPSF));
                    if (j & 1) acc1 += (double)pix;
                    else       acc0 += (double)pix;
                }
            }
            __syncthreads();   // all reads of this bank done before next reuse
        }
    }

    // ---- block reduction of double partials ----
    sd[t] = acc0 + acc1;
    __syncthreads();
    if (t < 112) sd[t] += sd[t + 112];
    __syncthreads();
    if (t < 56)  sd[t] += sd[t + 56];
    __syncthreads();
    if (t < 28)  sd[t] += sd[t + 28];
    __syncthreads();
    if (t < 14)  sd[t] += sd[t + 14];
    __syncthreads();
    if (t < 7)   sd[t] += sd[t + 7];
    __syncthreads();
    if (t == 0) {
        double s = sd[0];
        for (int k = 1; k < 7; k++) s += sd[k];
        g_ds2[p * 2 + half] = s;
    }
}

// ---------------- kernel 2: sqrt / normalize / cumsum / argmin ---------------
// ratio = 16/64 = 0.25 ; exponent = sqrt(0.25) = 0.5 -> dsp = sqrt(diff_score)
__global__ void select_kernel()
{
    const int b = threadIdx.x;
    if (b >= BATCH) return;

    double dsp[LFRM - 1];
    double s = 0.0;
    for (int l = 0; l < LFRM - 1; l++) {
        const int p = b * (LFRM - 1) + l;
        double d = sqrt(g_ds2[p * 2] + g_ds2[p * 2 + 1]);
        dsp[l] = d;
        s += d;
    }
    double cums[LFRM - 1];
    double c = 0.0;
    for (int l = 0; l < LFRM - 1; l++) {
        c += dsp[l] / s;
        cums[l] = c;
    }
    const float interval = 1.0f / (float)(MSEL - 1);
    for (int m = 0; m < MSEL; m++) {
        double target = (double)((float)m * interval);
        double best = 1e300;
        int bi = 0;
        for (int l = 0; l < LFRM - 1; l++) {
            double d = fabs(cums[l] - target);
            if (d < best) { best = d; bi = l; }   // strict '<' => first occurrence
        }
        g_idx[b * MSEL + m] = bi;
    }
}

// ---------------- kernel 3: gather selected frames ---------------------------
__global__ __launch_bounds__(256) void gather_kernel(const float* __restrict__ x,
                                                     float* __restrict__ out)
{
    const int bm = blockIdx.y;             // 0..127
    const int b  = bm >> 4;
    const int src = b * LFRM + g_idx[bm];
    const float4* sp = (const float4*)(x + (size_t)src * (CH * HWSZ));
    float4* dp = (float4*)(out + (size_t)bm * (CH * HWSZ));
    const int i = blockIdx.x * 256 + threadIdx.x;   // 147*256 = 37632 exact
    dp[i] = sp[i];
}

// ---------------- launcher ---------------------------------------------------
extern "C" void kernel_launch(void* const* d_in, const int* in_sizes, int n_in,
                              void* d_out, int out_size)
{
    const float* x = nullptr;
    const float* w = nullptr;
    for (int i = 0; i < n_in; i++) {
        if (in_sizes[i] == FRAMES * CH * HWSZ) x = (const float*)d_in[i];
        else if (in_sizes[i] == CH * 49)       w = (const float*)d_in[i];
    }

    pairdiff_kernel<<<dim3(2, PAIRS), 224>>>(x, w);
    select_kernel<<<1, 32>>>();
    gather_kernel<<<dim3(147, BATCH * MSEL), 256>>>(x, (float*)d_out);
}